// round 8
// baseline (speedup 1.0000x reference)
#include <cuda_runtime.h>
#include <math.h>
#include <stddef.h>

#define NCOL 32768
#define KAT  512
#define DIMD 64

// ---------------- static scratch ----------------
__device__ float g_Dn[DIMD * KAT];                  // normalized dictionary [64,512]
__device__ float g_G [KAT * KAT];                   // Gram [512,512]
__device__ float g_ZF[(size_t)DIMD * NCOL];         // zf raw buffer (= zp flattened)
__device__ float g_HB[(size_t)NCOL * KAT];          // h_bar [N,K]
__device__ int   g_cidx[NCOL * 8];                  // selected atoms per column
__device__ float g_cval[NCOL * 8];                  // coefficients per column
__device__ float g_ent[NCOL];                       // per-column entropy term
__device__ float g_lpart[1024];                     // per-block loss partials

// ---------------- K0: zero gamma region (float2: gamma is only 8B-aligned) ----------------
__global__ __launch_bounds__(256) void zero_gamma_kernel(float2* __restrict__ g)
{
    size_t i = (size_t)blockIdx.x * blockDim.x + threadIdx.x;
    size_t stride = (size_t)gridDim.x * blockDim.x;
    const size_t n2 = (size_t)KAT * NCOL / 2;
    float2 z = make_float2(0.f, 0.f);
    for (; i < n2; i += stride) g[i] = z;
}

// ---------------- K1: normalize dictionary columns ----------------
__global__ void normalize_kernel(const float* __restrict__ dict)
{
    int k = blockIdx.x * blockDim.x + threadIdx.x;
    if (k < KAT) {
        float s = 0.0f;
#pragma unroll
        for (int i = 0; i < DIMD; i++) { float v = dict[i * KAT + k]; s += v * v; }
        float nm = sqrtf(s);
#pragma unroll
        for (int i = 0; i < DIMD; i++) g_Dn[i * KAT + k] = dict[i * KAT + k] / nm;
    }
}

// ---------------- K2: Gram G = Dn^T Dn ----------------
__global__ __launch_bounds__(256) void gram_kernel()
{
    int t  = blockIdx.x * 256 + threadIdx.x;
    int k1 = t >> 9;
    int k2 = t & 511;
    float s = 0.0f;
#pragma unroll 8
    for (int i = 0; i < DIMD; i++)
        s = fmaf(g_Dn[i * KAT + k1], g_Dn[i * KAT + k2], s);
    g_G[t] = s;
}

// ---------------- K3: z_e [32,64,32,32] -> zp raw buffer g_ZF ----------------
__global__ __launch_bounds__(256) void transpose_kernel(const float* __restrict__ z_e)
{
    int bh = blockIdx.x;               // b*32 + h
    int b  = bh >> 5;
    int hh = bh & 31;
    __shared__ float tile[64][33];
    int tid = threadIdx.x;
    int c0 = tid >> 5;
    int w  = tid & 31;
#pragma unroll
    for (int cc = 0; cc < 64; cc += 8) {
        int c = cc + c0;
        tile[c][w] = z_e[(((size_t)b * 64 + c) * 32 + hh) * 32 + w];
    }
    __syncthreads();
    int c2 = tid & 63;
    int w0 = tid >> 6;
    size_t base = (size_t)bh * 2048;
#pragma unroll
    for (int ww = 0; ww < 32; ww += 4) {
        int w2 = ww + w0;
        g_ZF[base + (size_t)w2 * 64 + c2] = tile[c2][w2];
    }
}

// ---------------- K4: HB[n,k] = sum_i zf[i,n]*Dn[i,k] ----------------
__global__ __launch_bounds__(128) void hb_gemm_kernel()
{
    __shared__ float As[64][128];
    __shared__ float Bs[64][64];
    int n0 = blockIdx.x * 128;
    int k0 = blockIdx.y * 64;
    int tid = threadIdx.x;

#pragma unroll
    for (int v = 0; v < 16; v++) {
        int r = v * 4 + (tid >> 5);
        int c = (tid & 31) * 4;
        *reinterpret_cast<float4*>(&As[r][c]) =
            *reinterpret_cast<const float4*>(&g_ZF[(size_t)r * NCOL + n0 + c]);
    }
#pragma unroll
    for (int v = 0; v < 8; v++) {
        int r = v * 8 + (tid >> 4);
        int c = (tid & 15) * 4;
        *reinterpret_cast<float4*>(&Bs[r][c]) =
            *reinterpret_cast<const float4*>(&g_Dn[r * KAT + k0 + c]);
    }
    __syncthreads();

    int tx = tid & 7;
    int ty = tid >> 3;
    float acc[8][8];
#pragma unroll
    for (int r = 0; r < 8; r++)
#pragma unroll
        for (int c = 0; c < 8; c++) acc[r][c] = 0.0f;

#pragma unroll 8
    for (int i = 0; i < 64; i++) {
        float4 a0 = *reinterpret_cast<const float4*>(&As[i][ty * 8]);
        float4 a1 = *reinterpret_cast<const float4*>(&As[i][ty * 8 + 4]);
        float4 b0 = *reinterpret_cast<const float4*>(&Bs[i][tx * 8]);
        float4 b1 = *reinterpret_cast<const float4*>(&Bs[i][tx * 8 + 4]);
        float av[8] = {a0.x, a0.y, a0.z, a0.w, a1.x, a1.y, a1.z, a1.w};
        float bv[8] = {b0.x, b0.y, b0.z, b0.w, b1.x, b1.y, b1.z, b1.w};
#pragma unroll
        for (int r = 0; r < 8; r++)
#pragma unroll
            for (int c = 0; c < 8; c++) acc[r][c] = fmaf(av[r], bv[c], acc[r][c]);
    }
#pragma unroll
    for (int r = 0; r < 8; r++) {
        size_t row = (size_t)(n0 + ty * 8 + r) * KAT + k0 + tx * 8;
        *reinterpret_cast<float4*>(&g_HB[row]) =
            make_float4(acc[r][0], acc[r][1], acc[r][2], acc[r][3]);
        *reinterpret_cast<float4*>(&g_HB[row + 4]) =
            make_float4(acc[r][4], acc[r][5], acc[r][6], acc[r][7]);
    }
}

// select a[eb] from 16 register-resident values via SEL mux tree
__device__ __forceinline__ float extract16(const float (&a)[16], int eb)
{
    float b0 = (eb & 1) ? a[1]  : a[0];
    float b1 = (eb & 1) ? a[3]  : a[2];
    float b2 = (eb & 1) ? a[5]  : a[4];
    float b3 = (eb & 1) ? a[7]  : a[6];
    float b4 = (eb & 1) ? a[9]  : a[8];
    float b5 = (eb & 1) ? a[11] : a[10];
    float b6 = (eb & 1) ? a[13] : a[12];
    float b7 = (eb & 1) ? a[15] : a[14];
    float c0 = (eb & 2) ? b1 : b0;
    float c1 = (eb & 2) ? b3 : b2;
    float c2 = (eb & 2) ? b5 : b4;
    float c3 = (eb & 2) ? b7 : b6;
    float d0 = (eb & 4) ? c1 : c0;
    float d1 = (eb & 4) ? c3 : c2;
    return (eb & 8) ? d1 : d0;
}

// ---------------- K5: Batch-OMP, one warp per column ----------------
// v5 hybrid: Gram rows 0-2 in registers (carry 18/28 of the re-reads, zero
// crossbar cost), rows 3-6 in smem (8KB/warp -> 28 warps/SM). Arithmetic
// identical to v3/v4 (both measured rel_err 3.569e-7).
__global__ __launch_bounds__(64) void omp_kernel(float* __restrict__ gamma)
{
    __shared__ float sgrow[2 * 4 * 512];          // per-warp rows 3..6

    const int warp = threadIdx.x >> 5;
    const int lane = threadIdx.x & 31;
    const int n = blockIdx.x * 2 + warp;
    float* sg = sgrow + warp * 4 * 512;

    const float* hbp = g_HB + (size_t)n * KAT;

    // lane owns element j = t*128 + lane*4 + e (t=0..3, e=0..3); eb = t*4+e
    float hb[16];
#pragma unroll
    for (int t = 0; t < 4; t++) {
        float4 v = *reinterpret_cast<const float4*>(hbp + t * 128 + lane * 4);
        hb[4*t+0] = v.x; hb[4*t+1] = v.y; hb[4*t+2] = v.z; hb[4*t+3] = v.w;
    }

    unsigned mask = 0;
    float growr[3][16];    // register rows 0..2
    float Lm[36];          // packed lower-tri (off-diagonals used)
    float Ldinv[8];        // reciprocal diagonal
    float xsr[8];
    float y[8];            // forward-solve solution (incremental)
    int   idxr[8];
#pragma unroll
    for (int i = 0; i < 36; i++) Lm[i] = 0.0f;
#pragma unroll
    for (int i = 0; i < 8; i++) { xsr[i] = 0.0f; idxr[i] = 0; y[i] = 0.0f; Ldinv[i] = 1.0f; }

#pragma unroll
    for (int k = 1; k <= 8; k++) {
        // ---- masked argmax of |h|; h recomputed: reg rows then smem rows ----
        unsigned bestkey = 0u; int bj = 0x7fffffff;
#pragma unroll
        for (int t = 0; t < 4; t++) {
            int off = t * 128 + lane * 4;
            float v0 = hb[4*t+0], v1 = hb[4*t+1], v2 = hb[4*t+2], v3 = hb[4*t+3];
#pragma unroll
            for (int s = 0; s < 3; s++) {
                if (s < k - 1) {
                    float c = xsr[s];
                    v0 = fmaf(-c, growr[s][4*t+0], v0);
                    v1 = fmaf(-c, growr[s][4*t+1], v1);
                    v2 = fmaf(-c, growr[s][4*t+2], v2);
                    v3 = fmaf(-c, growr[s][4*t+3], v3);
                }
            }
#pragma unroll
            for (int s = 3; s < 7; s++) {
                if (s < k - 1) {
                    float4 gv = *reinterpret_cast<const float4*>(&sg[(s-3) * 512 + off]);
                    float c = xsr[s];
                    v0 = fmaf(-c, gv.x, v0);
                    v1 = fmaf(-c, gv.y, v1);
                    v2 = fmaf(-c, gv.z, v2);
                    v3 = fmaf(-c, gv.w, v3);
                }
            }
            float vv[4] = {v0, v1, v2, v3};
#pragma unroll
            for (int e = 0; e < 4; e++) {
                int eb = t * 4 + e;
                unsigned key = ((mask >> eb) & 1u) ? 0u
                             : (__float_as_uint(fabsf(vv[e])) + 1u);
                int j = off + e;
                if (key > bestkey) { bestkey = key; bj = j; }
            }
        }
        unsigned mk = __reduce_max_sync(0xffffffffu, bestkey);
        unsigned cand = (bestkey == mk) ? (unsigned)bj : 0xffffffffu;
        bj = (int)__reduce_min_sync(0xffffffffu, cand);

        if (((bj >> 2) & 31) == lane)
            mask |= 1u << ((((unsigned)bj >> 7) << 2) | ((unsigned)bj & 3u));
        idxr[k - 1] = bj;

        // ---- load new Gram row: rows 0-2 -> registers, rows 3-6 -> smem ----
        if (k <= 3) {
            const float* gr = g_G + (size_t)bj * KAT;
#pragma unroll
            for (int t = 0; t < 4; t++) {
                float4 gv = *reinterpret_cast<const float4*>(gr + t * 128 + lane * 4);
#pragma unroll
                for (int kk = 0; kk < 3; kk++) {
                    if (kk == k - 1) {
                        growr[kk][4*t+0] = gv.x; growr[kk][4*t+1] = gv.y;
                        growr[kk][4*t+2] = gv.z; growr[kk][4*t+3] = gv.w;
                    }
                }
            }
        } else if (k < 8) {
            const float* gr = g_G + (size_t)bj * KAT;
#pragma unroll
            for (int t = 0; t < 4; t++) {
                float4 gv = *reinterpret_cast<const float4*>(gr + t * 128 + lane * 4);
                *reinterpret_cast<float4*>(&sg[(k-4) * 512 + t * 128 + lane * 4]) = gv;
            }
        }
        __syncwarp();

        int eb = ((bj >> 7) << 2) | (bj & 3);    // warp-uniform
        int sl = (bj >> 2) & 31;

        // h_bar[bj] from register cache
        float hbv;
        {
            float hv = extract16(hb, eb);
            hbv = __shfl_sync(0xffffffffu, hv, sl);
        }

        // ---- Cholesky update; G[idx_s][bj]: regs via extract+shfl, smem via LDS ----
        if (k > 1) {
            float gsel[7];
#pragma unroll
            for (int i2 = 0; i2 < 3; i2++) {
                if (i2 < k - 1) {
                    float ev = extract16(growr[i2], eb);
                    gsel[i2] = __shfl_sync(0xffffffffu, ev, sl);
                }
            }
#pragma unroll
            for (int i2 = 3; i2 < 7; i2++)
                if (i2 < k - 1) gsel[i2] = sg[(i2-3) * 512 + bj];

            float w[7];
            float ss = 0.0f;
#pragma unroll
            for (int i2 = 0; i2 < 7; i2++) {
                if (i2 < k - 1) {
                    float a = gsel[i2];
#pragma unroll
                    for (int j2 = 0; j2 < 7; j2++)
                        if (j2 < i2) a -= Lm[i2 * (i2 + 1) / 2 + j2] * w[j2];
                    w[i2] = a * Ldinv[i2];
                    ss += w[i2] * w[i2];
                }
            }
            Ldinv[k - 1] = rsqrtf(1.0f - ss);
#pragma unroll
            for (int j2 = 0; j2 < 7; j2++)
                if (j2 < k - 1) Lm[(k - 1) * k / 2 + j2] = w[j2];
        }

        // ---- incremental forward solve: only y[k-1] is new ----
        {
            float a = hbv;
#pragma unroll
            for (int j2 = 0; j2 < 7; j2++)
                if (j2 < k - 1) a -= Lm[(k - 1) * k / 2 + j2] * y[j2];
            y[k - 1] = a * Ldinv[k - 1];
        }
        // ---- backward solve L^T x = y (full) ----
#pragma unroll
        for (int i2 = 7; i2 >= 0; i2--) {
            if (i2 < k) {
                float a = y[i2];
#pragma unroll
                for (int j2 = 0; j2 < 8; j2++)
                    if (j2 > i2 && j2 < k) a -= Lm[j2 * (j2 + 1) / 2 + i2] * xsr[j2];
                xsr[i2] = a * Ldinv[i2];
            }
        }
    }

    // epilogue (lane 0): codes, gamma scatter, entropy
    if (lane == 0) {
#pragma unroll
        for (int s = 0; s < 8; s++) {
            g_cidx[n * 8 + s] = idxr[s];
            g_cval[n * 8 + s] = xsr[s];
            gamma[(size_t)idxr[s] * NCOL + n] = xsr[s];
        }
        float mx = 0.0f;
#pragma unroll
        for (int s = 0; s < 8; s++) mx = fmaxf(mx, xsr[s]);
        float Z = 504.0f * expf(-mx);
#pragma unroll
        for (int s = 0; s < 8; s++) Z += expf(xsr[s] - mx);
        float p0 = expf(-mx) / Z;
        float S = 504.0f * p0 * logf(p0 + 1e-10f);
#pragma unroll
        for (int s = 0; s < 8; s++) {
            float p = expf(xsr[s] - mx) / Z;
            S += p * logf(p + 1e-10f);
        }
        g_ent[n] = S;
    }
}

// ---------------- K6: recon + zf output + loss partials ----------------
__global__ __launch_bounds__(256) void recon_kernel(float* __restrict__ out)
{
    int bh = blockIdx.x;
    int b  = bh >> 5;
    int hh = bh & 31;
    int i  = bh >> 4;
    int n0 = (bh * 2048) & (NCOL - 1);
    int tid = threadIdx.x;

    __shared__ float sDn[KAT];
    sDn[tid]       = g_Dn[i * KAT + tid];
    sDn[tid + 256] = g_Dn[i * KAT + tid + 256];
    __syncthreads();

    float* recon_out = out + 1;
    float* zf_out    = out + 1 + 2097152;

    float acc = 0.0f;
#pragma unroll
    for (int j = 0; j < 8; j++) {
        int t = j * 256 + tid;
        int n = n0 + t;
        int4   ci0 = *reinterpret_cast<const int4*>(&g_cidx[n * 8]);
        int4   ci1 = *reinterpret_cast<const int4*>(&g_cidx[n * 8 + 4]);
        float4 cv0 = *reinterpret_cast<const float4*>(&g_cval[n * 8]);
        float4 cv1 = *reinterpret_cast<const float4*>(&g_cval[n * 8 + 4]);
        float r = cv0.x * sDn[ci0.x] + cv0.y * sDn[ci0.y]
                + cv0.z * sDn[ci0.z] + cv0.w * sDn[ci0.w]
                + cv1.x * sDn[ci1.x] + cv1.y * sDn[ci1.y]
                + cv1.z * sDn[ci1.z] + cv1.w * sDn[ci1.w];
        float ze = g_ZF[(size_t)bh * 2048 + t];
        int c = t & 63;
        int w = t >> 6;
        size_t oidx = (((size_t)b * 64 + c) * 32 + hh) * 32 + w;
        recon_out[oidx] = r;
        zf_out[(size_t)bh * 2048 + t] = ze;
        float d = r - ze;
        acc = fmaf(d, d, acc);
    }

    __shared__ float red[256];
    red[tid] = acc;
    __syncthreads();
#pragma unroll
    for (int s = 128; s > 0; s >>= 1) {
        if (tid < s) red[tid] += red[tid + s];
        __syncthreads();
    }
    if (tid == 0) g_lpart[bh] = red[0];
}

// ---------------- K7: finalize loss + perplexity ----------------
__global__ __launch_bounds__(1024) void final_kernel(const float* __restrict__ beta,
                                                     float* __restrict__ out)
{
    int tid = threadIdx.x;
    float sl = g_lpart[tid];
    float se = 0.0f;
#pragma unroll
    for (int j = 0; j < 32; j++) se += g_ent[tid + j * 1024];

    __shared__ float rl[1024];
    __shared__ float re[1024];
    rl[tid] = sl; re[tid] = se;
    __syncthreads();
#pragma unroll
    for (int s = 512; s > 0; s >>= 1) {
        if (tid < s) { rl[tid] += rl[tid + s]; re[tid] += re[tid + s]; }
        __syncthreads();
    }
    if (tid == 0) {
        float e_mean = rl[0] / 2097152.0f;
        out[0] = e_mean * 0.25f + beta[0] * e_mean;
        out[4194305] = expf(-re[0] / 32768.0f);
    }
}

extern "C" void kernel_launch(void* const* d_in, const int* in_sizes, int n_in,
                              void* d_out, int out_size)
{
    const float* z_e  = (const float*)d_in[0];
    const float* dict = (const float*)d_in[1];
    const float* beta = (const float*)d_in[2];
    float* out = (float*)d_out;
    float* gamma = out + 4194306;

    zero_gamma_kernel<<<8192, 256>>>((float2*)gamma);
    normalize_kernel<<<2, 256>>>(dict);
    gram_kernel<<<1024, 256>>>();
    transpose_kernel<<<1024, 256>>>(z_e);
    hb_gemm_kernel<<<dim3(256, 8), 128>>>();
    omp_kernel<<<16384, 64>>>(gamma);
    recon_kernel<<<1024, 256>>>(out);
    final_kernel<<<1, 1024>>>(beta, out);
}

// round 11
// speedup vs baseline: 1.0376x; 1.0376x over previous
#include <cuda_runtime.h>
#include <math.h>
#include <stddef.h>

#define NCOL 32768
#define KAT  512
#define DIMD 64

// ---------------- static scratch ----------------
__device__ float g_Dn[DIMD * KAT];                  // normalized dictionary [64,512]
__device__ float g_G [KAT * KAT];                   // Gram [512,512]
__device__ float g_ZF[(size_t)DIMD * NCOL];         // zp flattened (raw reshape source)
__device__ float g_HB[(size_t)NCOL * KAT];          // h_bar [N,K]
__device__ int   g_cidx[NCOL * 8];                  // selected atoms per column
__device__ float g_cval[NCOL * 8];                  // coefficients per column
__device__ float g_ent[NCOL];                       // per-column entropy term
__device__ float g_lpart[1024];                     // per-block loss partials

// ---------------- K0: z_e [32,64,32,32] -> zp flat buffer; blocks 0-1 also normalize dict ----------------
__global__ __launch_bounds__(256) void transpose_norm_kernel(const float* __restrict__ z_e,
                                                             const float* __restrict__ dict)
{
    int bh = blockIdx.x;               // b*32 + h
    int tid = threadIdx.x;

    // side job: dictionary normalization (blocks 0,1 cover k=0..511)
    if (bh < 2) {
        int k = bh * 256 + tid;
        float s = 0.0f;
#pragma unroll
        for (int i = 0; i < DIMD; i++) { float v = dict[i * KAT + k]; s += v * v; }
        float nm = sqrtf(s);
#pragma unroll
        for (int i = 0; i < DIMD; i++) g_Dn[i * KAT + k] = dict[i * KAT + k] / nm;
    }

    int b  = bh >> 5;
    int hh = bh & 31;
    __shared__ float tile[64][33];
    int c0 = tid >> 5;
    int w  = tid & 31;
#pragma unroll
    for (int cc = 0; cc < 64; cc += 8) {
        int c = cc + c0;
        tile[c][w] = z_e[(((size_t)b * 64 + c) * 32 + hh) * 32 + w];
    }
    __syncthreads();
    int c2 = tid & 63;
    int w0 = tid >> 6;
    size_t base = (size_t)bh * 2048;
#pragma unroll
    for (int ww = 0; ww < 32; ww += 4) {
        int w2 = ww + w0;
        g_ZF[base + (size_t)w2 * 64 + c2] = tile[c2][w2];
    }
}

// ---------------- K1: Gram G = Dn^T Dn ----------------
__global__ __launch_bounds__(256) void gram_kernel()
{
    int t  = blockIdx.x * 256 + threadIdx.x;
    int k1 = t >> 9;
    int k2 = t & 511;
    float s = 0.0f;
#pragma unroll 8
    for (int i = 0; i < DIMD; i++)
        s = fmaf(g_Dn[i * KAT + k1], g_Dn[i * KAT + k2], s);
    g_G[t] = s;
}

// ---------------- K2: HB[n,k] = sum_i zf[i,n]*Dn[i,k]; also zeroes a gamma slice ----------------
__global__ __launch_bounds__(128) void hb_gemm_kernel(float2* __restrict__ gzero)
{
    __shared__ float As[64][128];
    __shared__ float Bs[64][64];
    int n0 = blockIdx.x * 128;
    int k0 = blockIdx.y * 64;
    int tid = threadIdx.x;

#pragma unroll
    for (int v = 0; v < 16; v++) {
        int r = v * 4 + (tid >> 5);
        int c = (tid & 31) * 4;
        *reinterpret_cast<float4*>(&As[r][c]) =
            *reinterpret_cast<const float4*>(&g_ZF[(size_t)r * NCOL + n0 + c]);
    }
#pragma unroll
    for (int v = 0; v < 8; v++) {
        int r = v * 8 + (tid >> 4);
        int c = (tid & 15) * 4;
        *reinterpret_cast<float4*>(&Bs[r][c]) =
            *reinterpret_cast<const float4*>(&g_Dn[r * KAT + k0 + c]);
    }
    __syncthreads();

    int tx = tid & 7;
    int ty = tid >> 3;
    float acc[8][8];
#pragma unroll
    for (int r = 0; r < 8; r++)
#pragma unroll
        for (int c = 0; c < 8; c++) acc[r][c] = 0.0f;

#pragma unroll 8
    for (int i = 0; i < 64; i++) {
        float4 a0 = *reinterpret_cast<const float4*>(&As[i][ty * 8]);
        float4 a1 = *reinterpret_cast<const float4*>(&As[i][ty * 8 + 4]);
        float4 b0 = *reinterpret_cast<const float4*>(&Bs[i][tx * 8]);
        float4 b1 = *reinterpret_cast<const float4*>(&Bs[i][tx * 8 + 4]);
        float av[8] = {a0.x, a0.y, a0.z, a0.w, a1.x, a1.y, a1.z, a1.w};
        float bv[8] = {b0.x, b0.y, b0.z, b0.w, b1.x, b1.y, b1.z, b1.w};
#pragma unroll
        for (int r = 0; r < 8; r++)
#pragma unroll
            for (int c = 0; c < 8; c++) acc[r][c] = fmaf(av[r], bv[c], acc[r][c]);
    }
#pragma unroll
    for (int r = 0; r < 8; r++) {
        size_t row = (size_t)(n0 + ty * 8 + r) * KAT + k0 + tx * 8;
        *reinterpret_cast<float4*>(&g_HB[row]) =
            make_float4(acc[r][0], acc[r][1], acc[r][2], acc[r][3]);
        *reinterpret_cast<float4*>(&g_HB[row + 4]) =
            make_float4(acc[r][4], acc[r][5], acc[r][6], acc[r][7]);
    }

    // fused gamma zeroing: 2048 blocks x 4096 float2 = full 512x32768 gamma
    {
        int bid = blockIdx.y * 256 + blockIdx.x;
        size_t base = (size_t)bid * 4096 + tid;
        float2 z = make_float2(0.f, 0.f);
#pragma unroll
        for (int v = 0; v < 32; v++) gzero[base + v * 128] = z;
    }
}

// select a[eb] from 16 register-resident values via SEL mux tree
__device__ __forceinline__ float extract16(const float (&a)[16], int eb)
{
    float b0 = (eb & 1) ? a[1]  : a[0];
    float b1 = (eb & 1) ? a[3]  : a[2];
    float b2 = (eb & 1) ? a[5]  : a[4];
    float b3 = (eb & 1) ? a[7]  : a[6];
    float b4 = (eb & 1) ? a[9]  : a[8];
    float b5 = (eb & 1) ? a[11] : a[10];
    float b6 = (eb & 1) ? a[13] : a[12];
    float b7 = (eb & 1) ? a[15] : a[14];
    float c0 = (eb & 2) ? b1 : b0;
    float c1 = (eb & 2) ? b3 : b2;
    float c2 = (eb & 2) ? b5 : b4;
    float c3 = (eb & 2) ? b7 : b6;
    float d0 = (eb & 4) ? c1 : c0;
    float d1 = (eb & 4) ? c3 : c2;
    return (eb & 8) ? d1 : d0;
}

// ---------------- K3: Batch-OMP, one warp per column (R7/231.6 version, unchanged) ----------------
__global__ __launch_bounds__(64) void omp_kernel(float* __restrict__ gamma)
{
    __shared__ float sgrow[2 * 7 * 512];          // per-warp 7 rows of 512

    const int warp = threadIdx.x >> 5;
    const int lane = threadIdx.x & 31;
    const int n = blockIdx.x * 2 + warp;
    float* sg = sgrow + warp * 7 * 512;

    const float* hbp = g_HB + (size_t)n * KAT;

    // lane owns element j = t*128 + lane*4 + e (t=0..3, e=0..3); eb = t*4+e
    float hb[16];
#pragma unroll
    for (int t = 0; t < 4; t++) {
        float4 v = *reinterpret_cast<const float4*>(hbp + t * 128 + lane * 4);
        hb[4*t+0] = v.x; hb[4*t+1] = v.y; hb[4*t+2] = v.z; hb[4*t+3] = v.w;
    }

    unsigned mask = 0;
    float Lm[36];          // packed lower-tri (off-diagonals used)
    float Ldinv[8];        // reciprocal diagonal
    float xsr[8];
    float y[8];            // forward-solve solution (incremental)
    int   idxr[8];
#pragma unroll
    for (int i = 0; i < 36; i++) Lm[i] = 0.0f;
#pragma unroll
    for (int i = 0; i < 8; i++) { xsr[i] = 0.0f; idxr[i] = 0; y[i] = 0.0f; Ldinv[i] = 1.0f; }

#pragma unroll
    for (int k = 1; k <= 8; k++) {
        // ---- masked argmax of |h|, h recomputed from smem-cached rows ----
        unsigned bestkey = 0u; int bj = 0x7fffffff;
#pragma unroll
        for (int t = 0; t < 4; t++) {
            int off = t * 128 + lane * 4;
            float v0 = hb[4*t+0], v1 = hb[4*t+1], v2 = hb[4*t+2], v3 = hb[4*t+3];
#pragma unroll
            for (int s = 0; s < 7; s++) {
                if (s < k - 1) {
                    float4 gv = *reinterpret_cast<const float4*>(&sg[s * 512 + off]);
                    float c = xsr[s];
                    v0 = fmaf(-c, gv.x, v0);
                    v1 = fmaf(-c, gv.y, v1);
                    v2 = fmaf(-c, gv.z, v2);
                    v3 = fmaf(-c, gv.w, v3);
                }
            }
            float vv[4] = {v0, v1, v2, v3};
#pragma unroll
            for (int e = 0; e < 4; e++) {
                int eb = t * 4 + e;
                unsigned key = ((mask >> eb) & 1u) ? 0u
                             : (__float_as_uint(fabsf(vv[e])) + 1u);
                int j = off + e;
                if (key > bestkey) { bestkey = key; bj = j; }
            }
        }
        unsigned mk = __reduce_max_sync(0xffffffffu, bestkey);
        unsigned cand = (bestkey == mk) ? (unsigned)bj : 0xffffffffu;
        bj = (int)__reduce_min_sync(0xffffffffu, cand);

        if (((bj >> 2) & 31) == lane)
            mask |= 1u << ((((unsigned)bj >> 7) << 2) | ((unsigned)bj & 3u));
        idxr[k - 1] = bj;

        // ---- stream new Gram row into smem (consumed next step) ----
        if (k < 8) {
            const float* gr = g_G + (size_t)bj * KAT;
#pragma unroll
            for (int t = 0; t < 4; t++) {
                float4 gv = *reinterpret_cast<const float4*>(gr + t * 128 + lane * 4);
                *reinterpret_cast<float4*>(&sg[(k-1) * 512 + t * 128 + lane * 4]) = gv;
            }
        }
        __syncwarp();

        int eb = ((bj >> 7) << 2) | (bj & 3);    // warp-uniform
        int sl = (bj >> 2) & 31;

        // h_bar[bj] from register cache
        float hbv;
        {
            float hv = extract16(hb, eb);
            hbv = __shfl_sync(0xffffffffu, hv, sl);
        }

        // ---- Cholesky update (G[idx][bj] via broadcast LDS) ----
        if (k > 1) {
            float w[7];
            float ss = 0.0f;
#pragma unroll
            for (int i2 = 0; i2 < 7; i2++) {
                if (i2 < k - 1) {
                    float a = sg[i2 * 512 + bj];
#pragma unroll
                    for (int j2 = 0; j2 < 7; j2++)
                        if (j2 < i2) a -= Lm[i2 * (i2 + 1) / 2 + j2] * w[j2];
                    w[i2] = a * Ldinv[i2];
                    ss += w[i2] * w[i2];
                }
            }
            Ldinv[k - 1] = rsqrtf(1.0f - ss);
#pragma unroll
            for (int j2 = 0; j2 < 7; j2++)
                if (j2 < k - 1) Lm[(k - 1) * k / 2 + j2] = w[j2];
        }

        // ---- incremental forward solve: only y[k-1] is new ----
        {
            float a = hbv;
#pragma unroll
            for (int j2 = 0; j2 < 7; j2++)
                if (j2 < k - 1) a -= Lm[(k - 1) * k / 2 + j2] * y[j2];
            y[k - 1] = a * Ldinv[k - 1];
        }
        // ---- backward solve L^T x = y (full) ----
#pragma unroll
        for (int i2 = 7; i2 >= 0; i2--) {
            if (i2 < k) {
                float a = y[i2];
#pragma unroll
                for (int j2 = 0; j2 < 8; j2++)
                    if (j2 > i2 && j2 < k) a -= Lm[j2 * (j2 + 1) / 2 + i2] * xsr[j2];
                xsr[i2] = a * Ldinv[i2];
            }
        }
    }

    // epilogue (lane 0): codes, gamma scatter, entropy
    if (lane == 0) {
#pragma unroll
        for (int s = 0; s < 8; s++) {
            g_cidx[n * 8 + s] = idxr[s];
            g_cval[n * 8 + s] = xsr[s];
            gamma[(size_t)idxr[s] * NCOL + n] = xsr[s];
        }
        float mx = 0.0f;
#pragma unroll
        for (int s = 0; s < 8; s++) mx = fmaxf(mx, xsr[s]);
        float Z = 504.0f * expf(-mx);
#pragma unroll
        for (int s = 0; s < 8; s++) Z += expf(xsr[s] - mx);
        float p0 = expf(-mx) / Z;
        float S = 504.0f * p0 * logf(p0 + 1e-10f);
#pragma unroll
        for (int s = 0; s < 8; s++) {
            float p = expf(xsr[s] - mx) / Z;
            S += p * logf(p + 1e-10f);
        }
        g_ent[n] = S;
    }
}

// ---------------- K4: recon + zf output + loss partials ----------------
__global__ __launch_bounds__(256) void recon_kernel(float* __restrict__ out)
{
    int bh = blockIdx.x;
    int b  = bh >> 5;
    int hh = bh & 31;
    int i  = bh >> 4;
    int n0 = (bh * 2048) & (NCOL - 1);
    int tid = threadIdx.x;

    __shared__ float sDn[KAT];
    sDn[tid]       = g_Dn[i * KAT + tid];
    sDn[tid + 256] = g_Dn[i * KAT + tid + 256];
    __syncthreads();

    float* recon_out = out + 1;
    float* zf_out    = out + 1 + 2097152;

    float acc = 0.0f;
#pragma unroll
    for (int j = 0; j < 8; j++) {
        int t = j * 256 + tid;
        int n = n0 + t;
        int4   ci0 = *reinterpret_cast<const int4*>(&g_cidx[n * 8]);
        int4   ci1 = *reinterpret_cast<const int4*>(&g_cidx[n * 8 + 4]);
        float4 cv0 = *reinterpret_cast<const float4*>(&g_cval[n * 8]);
        float4 cv1 = *reinterpret_cast<const float4*>(&g_cval[n * 8 + 4]);
        float r = cv0.x * sDn[ci0.x] + cv0.y * sDn[ci0.y]
                + cv0.z * sDn[ci0.z] + cv0.w * sDn[ci0.w]
                + cv1.x * sDn[ci1.x] + cv1.y * sDn[ci1.y]
                + cv1.z * sDn[ci1.z] + cv1.w * sDn[ci1.w];
        float ze = g_ZF[(size_t)bh * 2048 + t];
        int c = t & 63;
        int w = t >> 6;
        size_t oidx = (((size_t)b * 64 + c) * 32 + hh) * 32 + w;
        recon_out[oidx] = r;
        zf_out[(size_t)bh * 2048 + t] = ze;
        float d = r - ze;
        acc = fmaf(d, d, acc);
    }

    __shared__ float red[256];
    red[tid] = acc;
    __syncthreads();
#pragma unroll
    for (int s = 128; s > 0; s >>= 1) {
        if (tid < s) red[tid] += red[tid + s];
        __syncthreads();
    }
    if (tid == 0) g_lpart[bh] = red[0];
}

// ---------------- K5: finalize loss + perplexity ----------------
__global__ __launch_bounds__(1024) void final_kernel(const float* __restrict__ beta,
                                                     float* __restrict__ out)
{
    int tid = threadIdx.x;
    float sl = g_lpart[tid];
    float se = 0.0f;
#pragma unroll
    for (int j = 0; j < 32; j++) se += g_ent[tid + j * 1024];

    __shared__ float rl[1024];
    __shared__ float re[1024];
    rl[tid] = sl; re[tid] = se;
    __syncthreads();
#pragma unroll
    for (int s = 512; s > 0; s >>= 1) {
        if (tid < s) { rl[tid] += rl[tid + s]; re[tid] += re[tid + s]; }
        __syncthreads();
    }
    if (tid == 0) {
        float e_mean = rl[0] / 2097152.0f;
        out[0] = e_mean * 0.25f + beta[0] * e_mean;
        out[4194305] = expf(-re[0] / 32768.0f);
    }
}

extern "C" void kernel_launch(void* const* d_in, const int* in_sizes, int n_in,
                              void* d_out, int out_size)
{
    const float* z_e  = (const float*)d_in[0];
    const float* dict = (const float*)d_in[1];
    const float* beta = (const float*)d_in[2];
    float* out = (float*)d_out;
    float* gamma = out + 4194306;

    transpose_norm_kernel<<<1024, 256>>>(z_e, dict);   // idx 0
    gram_kernel<<<1024, 256>>>();                      // idx 1
    hb_gemm_kernel<<<dim3(256, 8), 128>>>((float2*)gamma); // idx 2 (+gamma zero)
    omp_kernel<<<16384, 64>>>(gamma);                  // idx 3  <- ncu slot
    recon_kernel<<<1024, 256>>>(out);                  // idx 4
    final_kernel<<<1, 1024>>>(beta, out);              // idx 5
}

// round 12
// speedup vs baseline: 1.1099x; 1.0697x over previous
#include <cuda_runtime.h>
#include <math.h>
#include <stddef.h>

#define NCOL 32768
#define KAT  512
#define DIMD 64

// ---------------- static scratch ----------------
__device__ float g_Dn[DIMD * KAT];                  // normalized dictionary [64,512]
__device__ float g_G [KAT * KAT];                   // Gram [512,512]
__device__ float g_ZF[(size_t)DIMD * NCOL];         // zp flattened (raw reshape source)
__device__ float g_HB[(size_t)NCOL * KAT];          // h_bar [N,K]
__device__ int   g_cidx[NCOL * 8];                  // selected atoms per column
__device__ float g_cval[NCOL * 8];                  // coefficients per column
__device__ float g_ent[NCOL];                       // per-column entropy term
__device__ float g_lpart[1024];                     // per-block loss partials

// ---------------- K0: z_e [32,64,32,32] -> zp flat buffer; blocks 0-1 also normalize dict ----------------
__global__ __launch_bounds__(256) void transpose_norm_kernel(const float* __restrict__ z_e,
                                                             const float* __restrict__ dict)
{
    int bh = blockIdx.x;               // b*32 + h
    int tid = threadIdx.x;

    // side job: dictionary normalization (blocks 0,1 cover k=0..511)
    if (bh < 2) {
        int k = bh * 256 + tid;
        float s = 0.0f;
#pragma unroll
        for (int i = 0; i < DIMD; i++) { float v = dict[i * KAT + k]; s += v * v; }
        float nm = sqrtf(s);
#pragma unroll
        for (int i = 0; i < DIMD; i++) g_Dn[i * KAT + k] = dict[i * KAT + k] / nm;
    }

    int b  = bh >> 5;
    int hh = bh & 31;
    __shared__ float tile[64][33];
    int c0 = tid >> 5;
    int w  = tid & 31;
#pragma unroll
    for (int cc = 0; cc < 64; cc += 8) {
        int c = cc + c0;
        tile[c][w] = z_e[(((size_t)b * 64 + c) * 32 + hh) * 32 + w];
    }
    __syncthreads();
    int c2 = tid & 63;
    int w0 = tid >> 6;
    size_t base = (size_t)bh * 2048;
#pragma unroll
    for (int ww = 0; ww < 32; ww += 4) {
        int w2 = ww + w0;
        g_ZF[base + (size_t)w2 * 64 + c2] = tile[c2][w2];
    }
}

// ---------------- K1: Gram G = Dn^T Dn ----------------
__global__ __launch_bounds__(256) void gram_kernel()
{
    int t  = blockIdx.x * 256 + threadIdx.x;
    int k1 = t >> 9;
    int k2 = t & 511;
    float s = 0.0f;
#pragma unroll 8
    for (int i = 0; i < DIMD; i++)
        s = fmaf(g_Dn[i * KAT + k1], g_Dn[i * KAT + k2], s);
    g_G[t] = s;
}

// ---------------- K2: HB[n,k] = sum_i zf[i,n]*Dn[i,k]; also zeroes a gamma slice ----------------
__global__ __launch_bounds__(128) void hb_gemm_kernel(float2* __restrict__ gzero)
{
    __shared__ float As[64][128];
    __shared__ float Bs[64][64];
    int n0 = blockIdx.x * 128;
    int k0 = blockIdx.y * 64;
    int tid = threadIdx.x;

#pragma unroll
    for (int v = 0; v < 16; v++) {
        int r = v * 4 + (tid >> 5);
        int c = (tid & 31) * 4;
        *reinterpret_cast<float4*>(&As[r][c]) =
            *reinterpret_cast<const float4*>(&g_ZF[(size_t)r * NCOL + n0 + c]);
    }
#pragma unroll
    for (int v = 0; v < 8; v++) {
        int r = v * 8 + (tid >> 4);
        int c = (tid & 15) * 4;
        *reinterpret_cast<float4*>(&Bs[r][c]) =
            *reinterpret_cast<const float4*>(&g_Dn[r * KAT + k0 + c]);
    }
    __syncthreads();

    int tx = tid & 7;
    int ty = tid >> 3;
    float acc[8][8];
#pragma unroll
    for (int r = 0; r < 8; r++)
#pragma unroll
        for (int c = 0; c < 8; c++) acc[r][c] = 0.0f;

#pragma unroll 8
    for (int i = 0; i < 64; i++) {
        float4 a0 = *reinterpret_cast<const float4*>(&As[i][ty * 8]);
        float4 a1 = *reinterpret_cast<const float4*>(&As[i][ty * 8 + 4]);
        float4 b0 = *reinterpret_cast<const float4*>(&Bs[i][tx * 8]);
        float4 b1 = *reinterpret_cast<const float4*>(&Bs[i][tx * 8 + 4]);
        float av[8] = {a0.x, a0.y, a0.z, a0.w, a1.x, a1.y, a1.z, a1.w};
        float bv[8] = {b0.x, b0.y, b0.z, b0.w, b1.x, b1.y, b1.z, b1.w};
#pragma unroll
        for (int r = 0; r < 8; r++)
#pragma unroll
            for (int c = 0; c < 8; c++) acc[r][c] = fmaf(av[r], bv[c], acc[r][c]);
    }
#pragma unroll
    for (int r = 0; r < 8; r++) {
        size_t row = (size_t)(n0 + ty * 8 + r) * KAT + k0 + tx * 8;
        *reinterpret_cast<float4*>(&g_HB[row]) =
            make_float4(acc[r][0], acc[r][1], acc[r][2], acc[r][3]);
        *reinterpret_cast<float4*>(&g_HB[row + 4]) =
            make_float4(acc[r][4], acc[r][5], acc[r][6], acc[r][7]);
    }

    // fused gamma zeroing: 2048 blocks x 4096 float2 = full 512x32768 gamma
    {
        int bid = blockIdx.y * 256 + blockIdx.x;
        size_t base = (size_t)bid * 4096 + tid;
        float2 z = make_float2(0.f, 0.f);
#pragma unroll
        for (int v = 0; v < 32; v++) gzero[base + v * 128] = z;
    }
}

// select a[eb] from 16 register-resident values via SEL mux tree
__device__ __forceinline__ float extract16(const float (&a)[16], int eb)
{
    float b0 = (eb & 1) ? a[1]  : a[0];
    float b1 = (eb & 1) ? a[3]  : a[2];
    float b2 = (eb & 1) ? a[5]  : a[4];
    float b3 = (eb & 1) ? a[7]  : a[6];
    float b4 = (eb & 1) ? a[9]  : a[8];
    float b5 = (eb & 1) ? a[11] : a[10];
    float b6 = (eb & 1) ? a[13] : a[12];
    float b7 = (eb & 1) ? a[15] : a[14];
    float c0 = (eb & 2) ? b1 : b0;
    float c1 = (eb & 2) ? b3 : b2;
    float c2 = (eb & 2) ? b5 : b4;
    float c3 = (eb & 2) ? b7 : b6;
    float d0 = (eb & 4) ? c1 : c0;
    float d1 = (eb & 4) ? c3 : c2;
    return (eb & 8) ? d1 : d0;
}

// ---------------- K3: Batch-OMP, one warp per column ----------------
// v6: rows 0-4 in smem (20KB/block -> 8 blocks/SM = 16 warps, RF-bound),
// rows 5-6 read directly from L2 in the argmax (3 of 28 re-reads);
// argmax key = raw |h| bits (masked -> 0, ties -> lowest index = exact
// jnp.argmax(|h*(~mask)|) semantics). FMA order s ascending unchanged ->
// selections bit-identical to the 225.8us version.
__global__ __launch_bounds__(64, 8) void omp_kernel(float* __restrict__ gamma)
{
    __shared__ float sgrow[2 * 5 * 512];          // per-warp rows 0..4

    const int warp = threadIdx.x >> 5;
    const int lane = threadIdx.x & 31;
    const int n = blockIdx.x * 2 + warp;
    float* sg = sgrow + warp * 5 * 512;

    const float* hbp = g_HB + (size_t)n * KAT;

    // lane owns element j = t*128 + lane*4 + e (t=0..3, e=0..3); eb = t*4+e
    float hb[16];
#pragma unroll
    for (int t = 0; t < 4; t++) {
        float4 v = *reinterpret_cast<const float4*>(hbp + t * 128 + lane * 4);
        hb[4*t+0] = v.x; hb[4*t+1] = v.y; hb[4*t+2] = v.z; hb[4*t+3] = v.w;
    }

    unsigned mask = 0;
    float Lm[36];          // packed lower-tri (off-diagonals used)
    float Ldinv[8];        // reciprocal diagonal
    float xsr[8];
    float y[8];            // forward-solve solution (incremental)
    int   idxr[8];
#pragma unroll
    for (int i = 0; i < 36; i++) Lm[i] = 0.0f;
#pragma unroll
    for (int i = 0; i < 8; i++) { xsr[i] = 0.0f; idxr[i] = 0; y[i] = 0.0f; Ldinv[i] = 1.0f; }

#pragma unroll
    for (int k = 1; k <= 8; k++) {
        // ---- masked argmax of |h|; h recomputed: smem rows 0-4, L2 rows 5-6 ----
        unsigned bestkey = 0u; int bj = 0x7fffffff;
#pragma unroll
        for (int t = 0; t < 4; t++) {
            int off = t * 128 + lane * 4;
            float v0 = hb[4*t+0], v1 = hb[4*t+1], v2 = hb[4*t+2], v3 = hb[4*t+3];
#pragma unroll
            for (int s = 0; s < 5; s++) {
                if (s < k - 1) {
                    float4 gv = *reinterpret_cast<const float4*>(&sg[s * 512 + off]);
                    float c = xsr[s];
                    v0 = fmaf(-c, gv.x, v0);
                    v1 = fmaf(-c, gv.y, v1);
                    v2 = fmaf(-c, gv.z, v2);
                    v3 = fmaf(-c, gv.w, v3);
                }
            }
#pragma unroll
            for (int s = 5; s < 7; s++) {
                if (s < k - 1) {
                    float4 gv = *reinterpret_cast<const float4*>(
                        g_G + (size_t)idxr[s] * KAT + off);
                    float c = xsr[s];
                    v0 = fmaf(-c, gv.x, v0);
                    v1 = fmaf(-c, gv.y, v1);
                    v2 = fmaf(-c, gv.z, v2);
                    v3 = fmaf(-c, gv.w, v3);
                }
            }
            float vv[4] = {v0, v1, v2, v3};
#pragma unroll
            for (int e = 0; e < 4; e++) {
                int eb = t * 4 + e;
                unsigned key = ((mask >> eb) & 1u) ? 0u
                             : __float_as_uint(fabsf(vv[e]));
                int j = off + e;
                if (key > bestkey) { bestkey = key; bj = j; }
            }
        }
        unsigned mk = __reduce_max_sync(0xffffffffu, bestkey);
        unsigned cand = (bestkey == mk) ? (unsigned)bj : 0xffffffffu;
        bj = (int)__reduce_min_sync(0xffffffffu, cand);

        if (((bj >> 2) & 31) == lane)
            mask |= 1u << ((((unsigned)bj >> 7) << 2) | ((unsigned)bj & 3u));
        idxr[k - 1] = bj;

        // ---- stream new Gram row into smem for slots 0..4 (rows 5,6 stay in L2) ----
        if (k <= 5) {
            const float* gr = g_G + (size_t)bj * KAT;
#pragma unroll
            for (int t = 0; t < 4; t++) {
                float4 gv = *reinterpret_cast<const float4*>(gr + t * 128 + lane * 4);
                *reinterpret_cast<float4*>(&sg[(k-1) * 512 + t * 128 + lane * 4]) = gv;
            }
        }
        __syncwarp();

        int eb = ((bj >> 7) << 2) | (bj & 3);    // warp-uniform
        int sl = (bj >> 2) & 31;

        // h_bar[bj] from register cache
        float hbv;
        {
            float hv = extract16(hb, eb);
            hbv = __shfl_sync(0xffffffffu, hv, sl);
        }

        // ---- Cholesky update (G[idx][bj]: smem rows via LDS, rows 5-6 via L2) ----
        if (k > 1) {
            float w[7];
            float ss = 0.0f;
#pragma unroll
            for (int i2 = 0; i2 < 7; i2++) {
                if (i2 < k - 1) {
                    float a = (i2 < 5) ? sg[i2 * 512 + bj]
                                       : g_G[(size_t)idxr[i2] * KAT + bj];
#pragma unroll
                    for (int j2 = 0; j2 < 7; j2++)
                        if (j2 < i2) a -= Lm[i2 * (i2 + 1) / 2 + j2] * w[j2];
                    w[i2] = a * Ldinv[i2];
                    ss += w[i2] * w[i2];
                }
            }
            Ldinv[k - 1] = rsqrtf(1.0f - ss);
#pragma unroll
            for (int j2 = 0; j2 < 7; j2++)
                if (j2 < k - 1) Lm[(k - 1) * k / 2 + j2] = w[j2];
        }

        // ---- incremental forward solve: only y[k-1] is new ----
        {
            float a = hbv;
#pragma unroll
            for (int j2 = 0; j2 < 7; j2++)
                if (j2 < k - 1) a -= Lm[(k - 1) * k / 2 + j2] * y[j2];
            y[k - 1] = a * Ldinv[k - 1];
        }
        // ---- backward solve L^T x = y (full) ----
#pragma unroll
        for (int i2 = 7; i2 >= 0; i2--) {
            if (i2 < k) {
                float a = y[i2];
#pragma unroll
                for (int j2 = 0; j2 < 8; j2++)
                    if (j2 > i2 && j2 < k) a -= Lm[j2 * (j2 + 1) / 2 + i2] * xsr[j2];
                xsr[i2] = a * Ldinv[i2];
            }
        }
    }

    // epilogue (lane 0): codes, gamma scatter, entropy
    if (lane == 0) {
#pragma unroll
        for (int s = 0; s < 8; s++) {
            g_cidx[n * 8 + s] = idxr[s];
            g_cval[n * 8 + s] = xsr[s];
            gamma[(size_t)idxr[s] * NCOL + n] = xsr[s];
        }
        float mx = 0.0f;
#pragma unroll
        for (int s = 0; s < 8; s++) mx = fmaxf(mx, xsr[s]);
        float Z = 504.0f * expf(-mx);
#pragma unroll
        for (int s = 0; s < 8; s++) Z += expf(xsr[s] - mx);
        float p0 = expf(-mx) / Z;
        float S = 504.0f * p0 * logf(p0 + 1e-10f);
#pragma unroll
        for (int s = 0; s < 8; s++) {
            float p = expf(xsr[s] - mx) / Z;
            S += p * logf(p + 1e-10f);
        }
        g_ent[n] = S;
    }
}

// ---------------- K4: recon + zf output + loss partials ----------------
__global__ __launch_bounds__(256) void recon_kernel(float* __restrict__ out)
{
    int bh = blockIdx.x;
    int b  = bh >> 5;
    int hh = bh & 31;
    int i  = bh >> 4;
    int n0 = (bh * 2048) & (NCOL - 1);
    int tid = threadIdx.x;

    __shared__ float sDn[KAT];
    sDn[tid]       = g_Dn[i * KAT + tid];
    sDn[tid + 256] = g_Dn[i * KAT + tid + 256];
    __syncthreads();

    float* recon_out = out + 1;
    float* zf_out    = out + 1 + 2097152;

    float acc = 0.0f;
#pragma unroll
    for (int j = 0; j < 8; j++) {
        int t = j * 256 + tid;
        int n = n0 + t;
        int4   ci0 = *reinterpret_cast<const int4*>(&g_cidx[n * 8]);
        int4   ci1 = *reinterpret_cast<const int4*>(&g_cidx[n * 8 + 4]);
        float4 cv0 = *reinterpret_cast<const float4*>(&g_cval[n * 8]);
        float4 cv1 = *reinterpret_cast<const float4*>(&g_cval[n * 8 + 4]);
        float r = cv0.x * sDn[ci0.x] + cv0.y * sDn[ci0.y]
                + cv0.z * sDn[ci0.z] + cv0.w * sDn[ci0.w]
                + cv1.x * sDn[ci1.x] + cv1.y * sDn[ci1.y]
                + cv1.z * sDn[ci1.z] + cv1.w * sDn[ci1.w];
        float ze = g_ZF[(size_t)bh * 2048 + t];
        int c = t & 63;
        int w = t >> 6;
        size_t oidx = (((size_t)b * 64 + c) * 32 + hh) * 32 + w;
        recon_out[oidx] = r;
        zf_out[(size_t)bh * 2048 + t] = ze;
        float d = r - ze;
        acc = fmaf(d, d, acc);
    }

    __shared__ float red[256];
    red[tid] = acc;
    __syncthreads();
#pragma unroll
    for (int s = 128; s > 0; s >>= 1) {
        if (tid < s) red[tid] += red[tid + s];
        __syncthreads();
    }
    if (tid == 0) g_lpart[bh] = red[0];
}

// ---------------- K5: finalize loss + perplexity ----------------
__global__ __launch_bounds__(1024) void final_kernel(const float* __restrict__ beta,
                                                     float* __restrict__ out)
{
    int tid = threadIdx.x;
    float sl = g_lpart[tid];
    float se = 0.0f;
#pragma unroll
    for (int j = 0; j < 32; j++) se += g_ent[tid + j * 1024];

    __shared__ float rl[1024];
    __shared__ float re[1024];
    rl[tid] = sl; re[tid] = se;
    __syncthreads();
#pragma unroll
    for (int s = 512; s > 0; s >>= 1) {
        if (tid < s) { rl[tid] += rl[tid + s]; re[tid] += re[tid + s]; }
        __syncthreads();
    }
    if (tid == 0) {
        float e_mean = rl[0] / 2097152.0f;
        out[0] = e_mean * 0.25f + beta[0] * e_mean;
        out[4194305] = expf(-re[0] / 32768.0f);
    }
}

extern "C" void kernel_launch(void* const* d_in, const int* in_sizes, int n_in,
                              void* d_out, int out_size)
{
    const float* z_e  = (const float*)d_in[0];
    const float* dict = (const float*)d_in[1];
    const float* beta = (const float*)d_in[2];
    float* out = (float*)d_out;
    float* gamma = out + 4194306;

    transpose_norm_kernel<<<1024, 256>>>(z_e, dict);   // idx 0
    gram_kernel<<<1024, 256>>>();                      // idx 1
    hb_gemm_kernel<<<dim3(256, 8), 128>>>((float2*)gamma); // idx 2 (+gamma zero)
    omp_kernel<<<16384, 64>>>(gamma);                  // idx 3  <- ncu slot
    recon_kernel<<<1024, 256>>>(out);                  // idx 4
    final_kernel<<<1, 1024>>>(beta, out);              // idx 5
}